// round 8
// baseline (speedup 1.0000x reference)
#include <cuda_runtime.h>

// ---------------------------------------------------------------------------
// Tree3 fused, round 8: conv channel-pair register tiling — one task computes
// 2 channels from one shared input window (halves conv LDS issue count).
// Tree phase = R7 (gi-major broadcast, m-split, shfl combine).
// ---------------------------------------------------------------------------

#define THREADS 512
#define BTOT 2048
#define NPAIR 2                    // image pairs per CTA (4 images)

// float2-unit strides
#define IMG_ROW_F2   34
#define IMG_PLANE_F2 1092
#define POOL_ROW_F2  15
#define POOL_CH_F2   211

#define SZ_IMG_F2    (NPAIR*3*IMG_PLANE_F2)
#define SZ_POOL_F2   (NPAIR*45*POOL_CH_F2)
#define OFF_POOL_F2  SZ_IMG_F2
#define OFF_W        (2*(SZ_IMG_F2 + SZ_POOL_F2))
#define OFF_CB       (OFF_W + 1128)
#define OFF_T        (OFF_CB + 48)
#define SMEM_FLOATS  (OFF_T + 4*336)

__device__ __forceinline__ float2 ffma2(float2 a, float2 b, float2 c) {
    unsigned long long au = *reinterpret_cast<unsigned long long*>(&a);
    unsigned long long bu = *reinterpret_cast<unsigned long long*>(&b);
    unsigned long long cu = *reinterpret_cast<unsigned long long*>(&c);
    unsigned long long du;
    asm("fma.rn.f32x2 %0, %1, %2, %3;" : "=l"(du) : "l"(au), "l"(bu), "l"(cu));
    return *reinterpret_cast<float2*>(&du);
}

__device__ __forceinline__ float sigmoidf_fast(float v) {
    return __fdividef(1.0f, 1.0f + __expf(-v));
}

// Column-subpass of the 5x5 conv over an image pair, TWO channels sharing the
// same input window. NC conv columns x 2 conv rows -> NC/2 pooled per channel.
template<int NC>
__device__ __forceinline__ void conv_block2(const float2* __restrict__ ib,
                                            const float*  __restrict__ wb0,
                                            const float*  __restrict__ wb1,
                                            float2* __restrict__ pm0,
                                            float2* __restrict__ pm1)
{
    constexpr int NF4 = (NC + 5) / 2;       // float4 loads per row
    float2 A0[NC], A1[NC], B0[NC], B1[NC];
    #pragma unroll
    for (int k = 0; k < NC; k++) {
        A0[k] = make_float2(0.f, 0.f); A1[k] = make_float2(0.f, 0.f);
        B0[k] = make_float2(0.f, 0.f); B1[k] = make_float2(0.f, 0.f);
    }

    float2 w0[5], w1[5];
    #pragma unroll
    for (int r = 0; r < 6; r++) {
        float2 P[2 * NF4];
        const float4* rp = (const float4*)(ib + r * IMG_ROW_F2);
        #pragma unroll
        for (int u = 0; u < NF4; u++) {
            float4 q = rp[u];
            P[2*u]   = make_float2(q.x, q.y);
            P[2*u+1] = make_float2(q.z, q.w);
        }
        if (r > 0) {                        // weights of row r-1 still live
            #pragma unroll
            for (int kx = 0; kx < 5; kx++)
                #pragma unroll
                for (int ox = 0; ox < NC; ox++) {
                    A1[ox] = ffma2(P[ox + kx], w0[kx], A1[ox]);
                    B1[ox] = ffma2(P[ox + kx], w1[kx], B1[ox]);
                }
        }
        if (r < 5) {
            #pragma unroll
            for (int kx = 0; kx < 5; kx++) {
                float a = wb0[r * 5 + kx];
                float b = wb1[r * 5 + kx];
                w0[kx] = make_float2(a, a);
                w1[kx] = make_float2(b, b);
            }
            #pragma unroll
            for (int kx = 0; kx < 5; kx++)
                #pragma unroll
                for (int ox = 0; ox < NC; ox++) {
                    A0[ox] = ffma2(P[ox + kx], w0[kx], A0[ox]);
                    B0[ox] = ffma2(P[ox + kx], w1[kx], B0[ox]);
                }
        }
    }

    #pragma unroll
    for (int pj = 0; pj < NC / 2; pj++) {
        pm0[pj] = make_float2(
            fmaxf(fmaxf(A0[2*pj].x, A0[2*pj+1].x), fmaxf(A1[2*pj].x, A1[2*pj+1].x)),
            fmaxf(fmaxf(A0[2*pj].y, A0[2*pj+1].y), fmaxf(A1[2*pj].y, A1[2*pj+1].y)));
        pm1[pj] = make_float2(
            fmaxf(fmaxf(B0[2*pj].x, B0[2*pj+1].x), fmaxf(B1[2*pj].x, B1[2*pj+1].x)),
            fmaxf(fmaxf(B0[2*pj].y, B0[2*pj+1].y), fmaxf(B1[2*pj].y, B1[2*pj+1].y)));
    }
}

__global__ __launch_bounds__(THREADS, 1)
void tree3_fused(const float* __restrict__ x,
                 const float* __restrict__ conv_w,
                 const float* __restrict__ conv_b,
                 const float* __restrict__ tree_w,
                 const float* __restrict__ tree_b,
                 const float* __restrict__ fc_w,
                 const float* __restrict__ fc_b,
                 float* __restrict__ out)
{
    extern __shared__ __align__(16) float sm[];
    float2* s_img  = reinterpret_cast<float2*>(sm);
    float2* s_pool = reinterpret_cast<float2*>(sm) + OFF_POOL_F2;
    float*  s_w    = sm + OFF_W;
    float*  s_cb   = sm + OFF_CB;
    float*  s_t    = sm + OFF_T;

    const int tid = threadIdx.x;
    const int b0  = blockIdx.x * (2 * NPAIR);

    // ---- stage conv weights + bias ----
    for (int idx = tid; idx < 1125; idx += THREADS) s_w[idx] = conv_w[idx];
    if (tid < 45) s_cb[tid] = conv_b[tid];

    // ---- stage images pairwise-interleaved (float4 in/out) ----
    for (int idx = tid; idx < NPAIR * 3 * 32 * 8; idx += THREADS) {
        int grp  = idx & 7;
        int row  = (idx >> 3) & 31;
        int gch  = (idx >> 8) % 3;
        int pair = idx / (3 * 32 * 8);
        const float* pA = x + (size_t)(b0 + 2 * pair) * 3072
                            + gch * 1024 + row * 32 + grp * 4;
        float4 a = *(const float4*)pA;
        float4 b = *(const float4*)(pA + 3072);
        float4* dst = (float4*)(s_img + (pair * 3 + gch) * IMG_PLANE_F2
                                      + row * IMG_ROW_F2 + grp * 4);
        dst[0] = make_float4(a.x, b.x, a.y, b.y);
        dst[1] = make_float4(a.z, b.z, a.w, b.w);
    }
    __syncthreads();

    // ---- phase 1: conv, 2 channels per task sharing one window ----
    // task = (pair, half, pi, g, blk): 2*2*14*3*8 = 1344
    for (int task = tid; task < 1344; task += THREADS) {
        int blk   = task & 7;
        int rest  = task >> 3;
        int g     = rest % 3;
        int rest2 = rest / 3;
        int pi    = rest2 % 14;
        int rest3 = rest2 / 14;
        int half  = rest3 & 1;
        int pair  = rest3 >> 1;

        int cb0 = (blk == 7) ? 13 : blk * 2;   // blk6:{12,13} blk7:{13,14} overlap
        int c0  = g * 15 + cb0;

        const float*  wb0 = s_w + c0 * 25;
        const float2* ib  = s_img + (pair * 3 + g) * IMG_PLANE_F2
                                  + (pi * 2) * IMG_ROW_F2 + half * 14;

        float bias0 = s_cb[c0];
        float bias1 = s_cb[c0 + 1];
        float2* pb0 = s_pool + (pair * 45 + c0) * POOL_CH_F2
                             + pi * POOL_ROW_F2 + half * 7;
        float2* pb1 = pb0 + POOL_CH_F2;

        {
            float2 pm0[4], pm1[4];
            conv_block2<8>(ib, wb0, wb0 + 25, pm0, pm1);
            #pragma unroll
            for (int pj = 0; pj < 4; pj++) {
                pb0[pj] = make_float2(sigmoidf_fast(pm0[pj].x + bias0),
                                      sigmoidf_fast(pm0[pj].y + bias0));
                pb1[pj] = make_float2(sigmoidf_fast(pm1[pj].x + bias1),
                                      sigmoidf_fast(pm1[pj].y + bias1));
            }
        }
        {
            float2 pm0[3], pm1[3];
            conv_block2<6>(ib + 8, wb0, wb0 + 25, pm0, pm1);
            #pragma unroll
            for (int pj = 0; pj < 3; pj++) {
                pb0[4 + pj] = make_float2(sigmoidf_fast(pm0[pj].x + bias0),
                                          sigmoidf_fast(pm0[pj].y + bias0));
                pb1[4 + pj] = make_float2(sigmoidf_fast(pm1[pj].x + bias1),
                                          sigmoidf_fast(pm1[pj].y + bias1));
            }
        }
    }
    __syncthreads();

    // ---- phase 2: tree einsum (R7: gi-major, m-split, shfl combine) ----
    for (int t = tid; t < 21 * 32; t += THREADS) {
        int gi  = t >> 5;
        int sub = t & 31;
        int f   = sub >> 1;
        int mh  = sub & 1;
        int g   = gi / 7;
        int i   = gi % 7;

        int m0 = mh ? 8 : 0;
        int m1 = mh ? 15 : 8;

        const float4* wp = (const float4*)tree_w + (f * 2205 + g * 49 + i * 7);

        float2 a0 = make_float2(0.f, 0.f), a1 = a0;
        float2 c0 = a0, c1 = a0;

        for (int m = m0; m < m1; m++) {
            const float4* wm = wp + m * 147;
            int ch = g * 15 + m;
            const float2* q0 = s_pool + ch * POOL_CH_F2
                                      + (2 * i) * POOL_ROW_F2;
            const float2* q1 = q0 + 45 * POOL_CH_F2;
            #pragma unroll
            for (int j = 0; j < 7; j++) {
                float4 w = wm[j];
                float2 wx = make_float2(w.x, w.x);
                float2 wy = make_float2(w.y, w.y);
                float2 wz = make_float2(w.z, w.z);
                float2 ww = make_float2(w.w, w.w);
                a0 = ffma2(q0[2*j],                wx, a0);
                a0 = ffma2(q0[2*j + 1],            wy, a0);
                a1 = ffma2(q0[2*j + POOL_ROW_F2],  wz, a1);
                a1 = ffma2(q0[2*j + POOL_ROW_F2+1],ww, a1);
                c0 = ffma2(q1[2*j],                wx, c0);
                c0 = ffma2(q1[2*j + 1],            wy, c0);
                c1 = ffma2(q1[2*j + POOL_ROW_F2],  wz, c1);
                c1 = ffma2(q1[2*j + POOL_ROW_F2+1],ww, c1);
            }
        }

        float r0x = a0.x + a1.x, r0y = a0.y + a1.y;
        float r1x = c0.x + c1.x, r1y = c0.y + c1.y;
        r0x += __shfl_xor_sync(0xffffffffu, r0x, 1);
        r0y += __shfl_xor_sync(0xffffffffu, r0y, 1);
        r1x += __shfl_xor_sync(0xffffffffu, r1x, 1);
        r1y += __shfl_xor_sync(0xffffffffu, r1y, 1);

        if (mh == 0) {
            int idx = f * 21 + gi;
            float tb = tree_b[idx];
            s_t[            idx] = sigmoidf_fast(r0x + tb);
            s_t[  336 +     idx] = sigmoidf_fast(r0y + tb);
            s_t[2*336 +     idx] = sigmoidf_fast(r1x + tb);
            s_t[3*336 +     idx] = sigmoidf_fast(r1y + tb);
        }
    }
    __syncthreads();

    // ---- phase 3: FC 336 -> 10 ----
    if (tid < 320) {
        int part  = tid & 7;
        int combo = tid >> 3;
        int img   = combo / 10;
        int o     = combo % 10;
        const float* tv = s_t + img * 336;
        const float* wv = fc_w + o * 336;
        float s = 0.f;
        for (int k = part; k < 336; k += 8)
            s = fmaf(tv[k], wv[k], s);
        s += __shfl_xor_sync(0xffffffffu, s, 1);
        s += __shfl_xor_sync(0xffffffffu, s, 2);
        s += __shfl_xor_sync(0xffffffffu, s, 4);
        if (part == 0)
            out[(b0 + img) * 10 + o] = s + fc_b[o];
    }
}

extern "C" void kernel_launch(void* const* d_in, const int* in_sizes, int n_in,
                              void* d_out, int out_size)
{
    const float* x      = (const float*)d_in[0];
    const float* conv_w = (const float*)d_in[1];
    const float* conv_b = (const float*)d_in[2];
    const float* tree_w = (const float*)d_in[3];
    const float* tree_b = (const float*)d_in[4];
    const float* fc_w   = (const float*)d_in[5];
    const float* fc_b   = (const float*)d_in[6];
    float* out = (float*)d_out;

    const int smem_bytes = SMEM_FLOATS * (int)sizeof(float);
    cudaFuncSetAttribute(tree3_fused,
                         cudaFuncAttributeMaxDynamicSharedMemorySize, smem_bytes);

    tree3_fused<<<BTOT / (2 * NPAIR), THREADS, smem_bytes>>>(
        x, conv_w, conv_b, tree_w, tree_b, fc_w, fc_b, out);
}

// round 9
// speedup vs baseline: 1.1293x; 1.1293x over previous
#include <cuda_runtime.h>

// ---------------------------------------------------------------------------
// Tree3 fused, round 9: R7 datapath, CTA halved to 1 image pair / 256 threads,
// 2 co-resident CTAs per SM overlap each other's barriers and low-parallelism
// phases. Packed f32x2 everywhere; two-subpass conv; gi-major tree phase.
// ---------------------------------------------------------------------------

#define THREADS 256
#define BTOT 2048

// float2-unit strides
#define IMG_ROW_F2   34
#define IMG_PLANE_F2 1092
#define POOL_ROW_F2  15
#define POOL_CH_F2   211

#define SZ_IMG_F2    (3*IMG_PLANE_F2)          // 3276
#define SZ_POOL_F2   (45*POOL_CH_F2)           // 9495
#define OFF_POOL_F2  SZ_IMG_F2
#define OFF_W        (2*(SZ_IMG_F2 + SZ_POOL_F2))  // 25542 floats
#define OFF_CB       (OFF_W + 1128)
#define OFF_T        (OFF_CB + 48)
#define SMEM_FLOATS  (OFF_T + 2*336)           // 27390 floats = 109,560 B

__device__ __forceinline__ float2 ffma2(float2 a, float2 b, float2 c) {
    unsigned long long au = *reinterpret_cast<unsigned long long*>(&a);
    unsigned long long bu = *reinterpret_cast<unsigned long long*>(&b);
    unsigned long long cu = *reinterpret_cast<unsigned long long*>(&c);
    unsigned long long du;
    asm("fma.rn.f32x2 %0, %1, %2, %3;" : "=l"(du) : "l"(au), "l"(bu), "l"(cu));
    return *reinterpret_cast<float2*>(&du);
}

__device__ __forceinline__ float sigmoidf_fast(float v) {
    return __fdividef(1.0f, 1.0f + __expf(-v));
}

// One column-subpass of the 5x5 conv over an image pair (R5/R7 proven form)
template<int NC>
__device__ __forceinline__ void conv_subpass(const float2* __restrict__ ib,
                                             const float*  __restrict__ wb,
                                             float2* __restrict__ pmax)
{
    constexpr int NF4 = (NC + 5) / 2;
    float2 acc0[NC], acc1[NC];
    #pragma unroll
    for (int k = 0; k < NC; k++) {
        acc0[k] = make_float2(0.f, 0.f);
        acc1[k] = make_float2(0.f, 0.f);
    }

    float2 wpk[5];
    #pragma unroll
    for (int r = 0; r < 6; r++) {
        float2 P[2 * NF4];
        const float4* rp = (const float4*)(ib + r * IMG_ROW_F2);
        #pragma unroll
        for (int u = 0; u < NF4; u++) {
            float4 q = rp[u];
            P[2*u]   = make_float2(q.x, q.y);
            P[2*u+1] = make_float2(q.z, q.w);
        }
        if (r > 0) {
            #pragma unroll
            for (int kx = 0; kx < 5; kx++)
                #pragma unroll
                for (int ox = 0; ox < NC; ox++)
                    acc1[ox] = ffma2(P[ox + kx], wpk[kx], acc1[ox]);
        }
        if (r < 5) {
            #pragma unroll
            for (int kx = 0; kx < 5; kx++) {
                float w = wb[r * 5 + kx];
                wpk[kx] = make_float2(w, w);
            }
            #pragma unroll
            for (int kx = 0; kx < 5; kx++)
                #pragma unroll
                for (int ox = 0; ox < NC; ox++)
                    acc0[ox] = ffma2(P[ox + kx], wpk[kx], acc0[ox]);
        }
    }

    #pragma unroll
    for (int pj = 0; pj < NC / 2; pj++) {
        float vx = fmaxf(fmaxf(acc0[2*pj].x, acc0[2*pj+1].x),
                         fmaxf(acc1[2*pj].x, acc1[2*pj+1].x));
        float vy = fmaxf(fmaxf(acc0[2*pj].y, acc0[2*pj+1].y),
                         fmaxf(acc1[2*pj].y, acc1[2*pj+1].y));
        pmax[pj] = make_float2(vx, vy);
    }
}

__global__ __launch_bounds__(THREADS, 2)
void tree3_fused(const float* __restrict__ x,
                 const float* __restrict__ conv_w,
                 const float* __restrict__ conv_b,
                 const float* __restrict__ tree_w,
                 const float* __restrict__ tree_b,
                 const float* __restrict__ fc_w,
                 const float* __restrict__ fc_b,
                 float* __restrict__ out)
{
    extern __shared__ __align__(16) float sm[];
    float2* s_img  = reinterpret_cast<float2*>(sm);               // [3][1092]
    float2* s_pool = reinterpret_cast<float2*>(sm) + OFF_POOL_F2; // [45][211]
    float*  s_w    = sm + OFF_W;
    float*  s_cb   = sm + OFF_CB;
    float*  s_t    = sm + OFF_T;

    const int tid = threadIdx.x;
    const int b0  = blockIdx.x * 2;           // one image pair per CTA

    // ---- stage conv weights + bias ----
    for (int idx = tid; idx < 1125; idx += THREADS) s_w[idx] = conv_w[idx];
    if (tid < 45) s_cb[tid] = conv_b[tid];

    // ---- stage the image pair, interleaved (float4 in/out) ----
    for (int idx = tid; idx < 3 * 32 * 8; idx += THREADS) {
        int grp = idx & 7;
        int row = (idx >> 3) & 31;
        int gch = idx >> 8;                    // 0..2
        const float* pA = x + (size_t)b0 * 3072 + gch * 1024 + row * 32 + grp * 4;
        float4 a = *(const float4*)pA;
        float4 b = *(const float4*)(pA + 3072);
        float4* dst = (float4*)(s_img + gch * IMG_PLANE_F2
                                      + row * IMG_ROW_F2 + grp * 4);
        dst[0] = make_float4(a.x, b.x, a.y, b.y);
        dst[1] = make_float4(a.z, b.z, a.w, b.w);
    }
    __syncthreads();

    // ---- phase 1: packed conv + sigmoid(max-pool) ----
    // task = (pi, half, c): 14*2*45 = 1260 -> 4.92 passes at 256 threads
    for (int task = tid; task < 45 * 28; task += THREADS) {
        int c    = task % 45;
        int rest = task / 45;                  // [0,28)
        int half = rest & 1;
        int pi   = rest >> 1;

        int g  = c / 15;
        const float*  wb = s_w + c * 25;
        const float2* ib = s_img + g * IMG_PLANE_F2
                                 + (pi * 2) * IMG_ROW_F2 + half * 14;

        float2 pmax[7];
        conv_subpass<8>(ib,     wb, pmax);
        conv_subpass<6>(ib + 8, wb, pmax + 4);

        float bias = s_cb[c];
        float2* pb = s_pool + c * POOL_CH_F2 + pi * POOL_ROW_F2 + half * 7;
        #pragma unroll
        for (int pj = 0; pj < 7; pj++)
            pb[pj] = make_float2(sigmoidf_fast(pmax[pj].x + bias),
                                 sigmoidf_fast(pmax[pj].y + bias));
    }
    __syncthreads();

    // ---- phase 2: tree einsum, gi-major lanes (pool LDS broadcasts), ----
    // ---- m split across lane pairs, shfl_xor(1) combine.             ----
    for (int t = tid; t < 21 * 32; t += THREADS) {
        int gi  = t >> 5;                      // 0..20, warp-uniform
        int sub = t & 31;
        int f   = sub >> 1;
        int mh  = sub & 1;
        int g   = gi / 7;
        int i   = gi % 7;

        int m0 = mh ? 8 : 0;
        int m1 = mh ? 15 : 8;

        const float4* wp = (const float4*)tree_w + (f * 2205 + g * 49 + i * 7);

        float2 a0 = make_float2(0.f, 0.f), a1 = a0;

        for (int m = m0; m < m1; m++) {
            const float4* wm = wp + m * 147;
            int ch = g * 15 + m;
            const float2* q0 = s_pool + ch * POOL_CH_F2 + (2 * i) * POOL_ROW_F2;
            #pragma unroll
            for (int j = 0; j < 7; j++) {
                float4 w = wm[j];
                a0 = ffma2(q0[2*j],                 make_float2(w.x, w.x), a0);
                a0 = ffma2(q0[2*j + 1],             make_float2(w.y, w.y), a0);
                a1 = ffma2(q0[2*j + POOL_ROW_F2],   make_float2(w.z, w.z), a1);
                a1 = ffma2(q0[2*j + POOL_ROW_F2+1], make_float2(w.w, w.w), a1);
            }
        }

        float rx = a0.x + a1.x;
        float ry = a0.y + a1.y;
        rx += __shfl_xor_sync(0xffffffffu, rx, 1);
        ry += __shfl_xor_sync(0xffffffffu, ry, 1);

        if (mh == 0) {
            int idx = f * 21 + gi;             // tree_b / FC ordering
            float tb = tree_b[idx];
            s_t[      idx] = sigmoidf_fast(rx + tb);
            s_t[336 + idx] = sigmoidf_fast(ry + tb);
        }
    }
    __syncthreads();

    // ---- phase 3: FC 336 -> 10 (2 imgs x 10 outs x 8 parts = 160 thr) ----
    if (tid < 160) {
        int part  = tid & 7;
        int combo = tid >> 3;                  // 0..19
        int img   = combo / 10;
        int o     = combo % 10;
        const float* tv = s_t + img * 336;
        const float* wv = fc_w + o * 336;
        float s = 0.f;
        for (int k = part; k < 336; k += 8)
            s = fmaf(tv[k], wv[k], s);
        s += __shfl_xor_sync(0xffffffffu, s, 1);
        s += __shfl_xor_sync(0xffffffffu, s, 2);
        s += __shfl_xor_sync(0xffffffffu, s, 4);
        if (part == 0)
            out[(b0 + img) * 10 + o] = s + fc_b[o];
    }
}

extern "C" void kernel_launch(void* const* d_in, const int* in_sizes, int n_in,
                              void* d_out, int out_size)
{
    const float* x      = (const float*)d_in[0];
    const float* conv_w = (const float*)d_in[1];
    const float* conv_b = (const float*)d_in[2];
    const float* tree_w = (const float*)d_in[3];
    const float* tree_b = (const float*)d_in[4];
    const float* fc_w   = (const float*)d_in[5];
    const float* fc_b   = (const float*)d_in[6];
    float* out = (float*)d_out;

    const int smem_bytes = SMEM_FLOATS * (int)sizeof(float);
    cudaFuncSetAttribute(tree3_fused,
                         cudaFuncAttributeMaxDynamicSharedMemorySize, smem_bytes);

    tree3_fused<<<BTOT / 2, THREADS, smem_bytes>>>(
        x, conv_w, conv_b, tree_w, tree_b, fc_w, fc_b, out);
}

// round 10
// speedup vs baseline: 1.2943x; 1.1461x over previous
#include <cuda_runtime.h>

// ---------------------------------------------------------------------------
// Tree3 fused, round 10: R9 conv/FC phases. Tree phase rebuilt GEMM-style:
// one warp per gi, lanes are k-elements (m,j,ki,kj) -> coalesced tree_w LDG
// (consecutive floats across lanes) + one pool LDS per k reused for all 16 f.
// Butterfly-reduce 16 accumulators, lane f stores output f.
// ---------------------------------------------------------------------------

#define THREADS 256
#define BTOT 2048

// float2-unit strides
#define IMG_ROW_F2   34
#define IMG_PLANE_F2 1092
#define POOL_ROW_F2  15
#define POOL_CH_F2   211

#define SZ_IMG_F2    (3*IMG_PLANE_F2)
#define SZ_POOL_F2   (45*POOL_CH_F2)
#define OFF_POOL_F2  SZ_IMG_F2
#define OFF_W        (2*(SZ_IMG_F2 + SZ_POOL_F2))
#define OFF_CB       (OFF_W + 1128)
#define OFF_T        (OFF_CB + 48)
#define SMEM_FLOATS  (OFF_T + 2*336)           // ~109.6 KB

__device__ __forceinline__ float2 ffma2(float2 a, float2 b, float2 c) {
    unsigned long long au = *reinterpret_cast<unsigned long long*>(&a);
    unsigned long long bu = *reinterpret_cast<unsigned long long*>(&b);
    unsigned long long cu = *reinterpret_cast<unsigned long long*>(&c);
    unsigned long long du;
    asm("fma.rn.f32x2 %0, %1, %2, %3;" : "=l"(du) : "l"(au), "l"(bu), "l"(cu));
    return *reinterpret_cast<float2*>(&du);
}

__device__ __forceinline__ float sigmoidf_fast(float v) {
    return __fdividef(1.0f, 1.0f + __expf(-v));
}

// One column-subpass of the 5x5 conv over an image pair (proven R5/R7 form)
template<int NC>
__device__ __forceinline__ void conv_subpass(const float2* __restrict__ ib,
                                             const float*  __restrict__ wb,
                                             float2* __restrict__ pmax)
{
    constexpr int NF4 = (NC + 5) / 2;
    float2 acc0[NC], acc1[NC];
    #pragma unroll
    for (int k = 0; k < NC; k++) {
        acc0[k] = make_float2(0.f, 0.f);
        acc1[k] = make_float2(0.f, 0.f);
    }

    float2 wpk[5];
    #pragma unroll
    for (int r = 0; r < 6; r++) {
        float2 P[2 * NF4];
        const float4* rp = (const float4*)(ib + r * IMG_ROW_F2);
        #pragma unroll
        for (int u = 0; u < NF4; u++) {
            float4 q = rp[u];
            P[2*u]   = make_float2(q.x, q.y);
            P[2*u+1] = make_float2(q.z, q.w);
        }
        if (r > 0) {
            #pragma unroll
            for (int kx = 0; kx < 5; kx++)
                #pragma unroll
                for (int ox = 0; ox < NC; ox++)
                    acc1[ox] = ffma2(P[ox + kx], wpk[kx], acc1[ox]);
        }
        if (r < 5) {
            #pragma unroll
            for (int kx = 0; kx < 5; kx++) {
                float w = wb[r * 5 + kx];
                wpk[kx] = make_float2(w, w);
            }
            #pragma unroll
            for (int kx = 0; kx < 5; kx++)
                #pragma unroll
                for (int ox = 0; ox < NC; ox++)
                    acc0[ox] = ffma2(P[ox + kx], wpk[kx], acc0[ox]);
        }
    }

    #pragma unroll
    for (int pj = 0; pj < NC / 2; pj++) {
        float vx = fmaxf(fmaxf(acc0[2*pj].x, acc0[2*pj+1].x),
                         fmaxf(acc1[2*pj].x, acc1[2*pj+1].x));
        float vy = fmaxf(fmaxf(acc0[2*pj].y, acc0[2*pj+1].y),
                         fmaxf(acc1[2*pj].y, acc1[2*pj+1].y));
        pmax[pj] = make_float2(vx, vy);
    }
}

__global__ __launch_bounds__(THREADS, 2)
void tree3_fused(const float* __restrict__ x,
                 const float* __restrict__ conv_w,
                 const float* __restrict__ conv_b,
                 const float* __restrict__ tree_w,
                 const float* __restrict__ tree_b,
                 const float* __restrict__ fc_w,
                 const float* __restrict__ fc_b,
                 float* __restrict__ out)
{
    extern __shared__ __align__(16) float sm[];
    float2* s_img  = reinterpret_cast<float2*>(sm);
    float2* s_pool = reinterpret_cast<float2*>(sm) + OFF_POOL_F2;
    float*  s_w    = sm + OFF_W;
    float*  s_cb   = sm + OFF_CB;
    float*  s_t    = sm + OFF_T;

    const int tid  = threadIdx.x;
    const int lane = tid & 31;
    const int wid  = tid >> 5;
    const int b0   = blockIdx.x * 2;

    // ---- stage conv weights + bias ----
    for (int idx = tid; idx < 1125; idx += THREADS) s_w[idx] = conv_w[idx];
    if (tid < 45) s_cb[tid] = conv_b[tid];

    // ---- stage the image pair, interleaved (float4 in/out) ----
    for (int idx = tid; idx < 3 * 32 * 8; idx += THREADS) {
        int grp = idx & 7;
        int row = (idx >> 3) & 31;
        int gch = idx >> 8;
        const float* pA = x + (size_t)b0 * 3072 + gch * 1024 + row * 32 + grp * 4;
        float4 a = *(const float4*)pA;
        float4 b = *(const float4*)(pA + 3072);
        float4* dst = (float4*)(s_img + gch * IMG_PLANE_F2
                                      + row * IMG_ROW_F2 + grp * 4);
        dst[0] = make_float4(a.x, b.x, a.y, b.y);
        dst[1] = make_float4(a.z, b.z, a.w, b.w);
    }
    __syncthreads();

    // ---- phase 1: packed conv + sigmoid(max-pool) ----
    for (int task = tid; task < 45 * 28; task += THREADS) {
        int c    = task % 45;
        int rest = task / 45;
        int half = rest & 1;
        int pi   = rest >> 1;

        int g  = c / 15;
        const float*  wb = s_w + c * 25;
        const float2* ib = s_img + g * IMG_PLANE_F2
                                 + (pi * 2) * IMG_ROW_F2 + half * 14;

        float2 pmax[7];
        conv_subpass<8>(ib,     wb, pmax);
        conv_subpass<6>(ib + 8, wb, pmax + 4);

        float bias = s_cb[c];
        float2* pb = s_pool + c * POOL_CH_F2 + pi * POOL_ROW_F2 + half * 7;
        #pragma unroll
        for (int pj = 0; pj < 7; pj++)
            pb[pj] = make_float2(sigmoidf_fast(pmax[pj].x + bias),
                                 sigmoidf_fast(pmax[pj].y + bias));
    }
    __syncthreads();

    // ---- phase 2: tree einsum, one warp per gi, k-major lanes ----
    // k = (m, j, ki, kj) in [0,420): lane-consecutive k -> coalesced tree_w.
    for (int gi = wid; gi < 21; gi += THREADS / 32) {
        int g = gi / 7;
        int i = gi % 7;

        const float* twp = tree_w + g * 196 + i * 28;   // + m*588 + f*8820 + rest

        float2 acc[16];
        #pragma unroll
        for (int f = 0; f < 16; f++) acc[f] = make_float2(0.f, 0.f);

        #pragma unroll
        for (int c = 0; c < 14; c++) {
            int k   = c * 32 + lane;
            bool act = (k < 420);
            int m   = k / 28;
            int r   = k - m * 28;
            int j   = r >> 2;
            int ki  = (r >> 1) & 1;
            int kj  = r & 1;

            float2 pv = make_float2(0.f, 0.f);
            if (act)
                pv = s_pool[(g * 15 + m) * POOL_CH_F2
                            + (2 * i + ki) * POOL_ROW_F2 + (2 * j + kj)];

            const float* wl = twp + m * 588 + j * 4 + ki * 2 + kj;
            #pragma unroll
            for (int f = 0; f < 16; f++) {
                float w = act ? __ldg(wl + f * 8820) : 0.f;
                acc[f] = ffma2(pv, make_float2(w, w), acc[f]);
            }
        }

        // butterfly-reduce each acc[f]; lane f computes sigmoid + stores
        #pragma unroll
        for (int f = 0; f < 16; f++) {
            float ax = acc[f].x, ay = acc[f].y;
            #pragma unroll
            for (int s = 16; s > 0; s >>= 1) {
                ax += __shfl_xor_sync(0xffffffffu, ax, s);
                ay += __shfl_xor_sync(0xffffffffu, ay, s);
            }
            if (lane == f) {
                int idx = f * 21 + gi;              // tree_b / FC ordering
                float tb = tree_b[idx];
                s_t[      idx] = sigmoidf_fast(ax + tb);
                s_t[336 + idx] = sigmoidf_fast(ay + tb);
            }
        }
    }
    __syncthreads();

    // ---- phase 3: FC 336 -> 10 ----
    if (tid < 160) {
        int part  = tid & 7;
        int combo = tid >> 3;
        int img   = combo / 10;
        int o     = combo % 10;
        const float* tv = s_t + img * 336;
        const float* wv = fc_w + o * 336;
        float s = 0.f;
        for (int k = part; k < 336; k += 8)
            s = fmaf(tv[k], wv[k], s);
        s += __shfl_xor_sync(0xffffffffu, s, 1);
        s += __shfl_xor_sync(0xffffffffu, s, 2);
        s += __shfl_xor_sync(0xffffffffu, s, 4);
        if (part == 0)
            out[(b0 + img) * 10 + o] = s + fc_b[o];
    }
}

extern "C" void kernel_launch(void* const* d_in, const int* in_sizes, int n_in,
                              void* d_out, int out_size)
{
    const float* x      = (const float*)d_in[0];
    const float* conv_w = (const float*)d_in[1];
    const float* conv_b = (const float*)d_in[2];
    const float* tree_w = (const float*)d_in[3];
    const float* tree_b = (const float*)d_in[4];
    const float* fc_w   = (const float*)d_in[5];
    const float* fc_b   = (const float*)d_in[6];
    float* out = (float*)d_out;

    const int smem_bytes = SMEM_FLOATS * (int)sizeof(float);
    cudaFuncSetAttribute(tree3_fused,
                         cudaFuncAttributeMaxDynamicSharedMemorySize, smem_bytes);

    tree3_fused<<<BTOT / 2, THREADS, smem_bytes>>>(
        x, conv_w, conv_b, tree_w, tree_b, fc_w, fc_b, out);
}

// round 11
// speedup vs baseline: 1.7839x; 1.3782x over previous
#include <cuda_runtime.h>

// ---------------------------------------------------------------------------
// Tree3 fused, round 11: R10 + phase-2 polish:
//  - m-loop with hoisted lane decode (kills per-chunk div/mod ALU)
//  - select-butterfly multi-value reduction: 32 shfl instead of 160
// Conv + FC phases unchanged from R10 (best).
// ---------------------------------------------------------------------------

#define THREADS 256
#define BTOT 2048

// float2-unit strides
#define IMG_ROW_F2   34
#define IMG_PLANE_F2 1092
#define POOL_ROW_F2  15
#define POOL_CH_F2   211

#define SZ_IMG_F2    (3*IMG_PLANE_F2)
#define SZ_POOL_F2   (45*POOL_CH_F2)
#define OFF_POOL_F2  SZ_IMG_F2
#define OFF_W        (2*(SZ_IMG_F2 + SZ_POOL_F2))
#define OFF_CB       (OFF_W + 1128)
#define OFF_T        (OFF_CB + 48)
#define SMEM_FLOATS  (OFF_T + 2*336)

__device__ __forceinline__ float2 ffma2(float2 a, float2 b, float2 c) {
    unsigned long long au = *reinterpret_cast<unsigned long long*>(&a);
    unsigned long long bu = *reinterpret_cast<unsigned long long*>(&b);
    unsigned long long cu = *reinterpret_cast<unsigned long long*>(&c);
    unsigned long long du;
    asm("fma.rn.f32x2 %0, %1, %2, %3;" : "=l"(du) : "l"(au), "l"(bu), "l"(cu));
    return *reinterpret_cast<float2*>(&du);
}

__device__ __forceinline__ float sigmoidf_fast(float v) {
    return __fdividef(1.0f, 1.0f + __expf(-v));
}

// One column-subpass of the 5x5 conv over an image pair (proven form)
template<int NC>
__device__ __forceinline__ void conv_subpass(const float2* __restrict__ ib,
                                             const float*  __restrict__ wb,
                                             float2* __restrict__ pmax)
{
    constexpr int NF4 = (NC + 5) / 2;
    float2 acc0[NC], acc1[NC];
    #pragma unroll
    for (int k = 0; k < NC; k++) {
        acc0[k] = make_float2(0.f, 0.f);
        acc1[k] = make_float2(0.f, 0.f);
    }

    float2 wpk[5];
    #pragma unroll
    for (int r = 0; r < 6; r++) {
        float2 P[2 * NF4];
        const float4* rp = (const float4*)(ib + r * IMG_ROW_F2);
        #pragma unroll
        for (int u = 0; u < NF4; u++) {
            float4 q = rp[u];
            P[2*u]   = make_float2(q.x, q.y);
            P[2*u+1] = make_float2(q.z, q.w);
        }
        if (r > 0) {
            #pragma unroll
            for (int kx = 0; kx < 5; kx++)
                #pragma unroll
                for (int ox = 0; ox < NC; ox++)
                    acc1[ox] = ffma2(P[ox + kx], wpk[kx], acc1[ox]);
        }
        if (r < 5) {
            #pragma unroll
            for (int kx = 0; kx < 5; kx++) {
                float w = wb[r * 5 + kx];
                wpk[kx] = make_float2(w, w);
            }
            #pragma unroll
            for (int kx = 0; kx < 5; kx++)
                #pragma unroll
                for (int ox = 0; ox < NC; ox++)
                    acc0[ox] = ffma2(P[ox + kx], wpk[kx], acc0[ox]);
        }
    }

    #pragma unroll
    for (int pj = 0; pj < NC / 2; pj++) {
        float vx = fmaxf(fmaxf(acc0[2*pj].x, acc0[2*pj+1].x),
                         fmaxf(acc1[2*pj].x, acc1[2*pj+1].x));
        float vy = fmaxf(fmaxf(acc0[2*pj].y, acc0[2*pj+1].y),
                         fmaxf(acc1[2*pj].y, acc1[2*pj+1].y));
        pmax[pj] = make_float2(vx, vy);
    }
}

__global__ __launch_bounds__(THREADS, 2)
void tree3_fused(const float* __restrict__ x,
                 const float* __restrict__ conv_w,
                 const float* __restrict__ conv_b,
                 const float* __restrict__ tree_w,
                 const float* __restrict__ tree_b,
                 const float* __restrict__ fc_w,
                 const float* __restrict__ fc_b,
                 float* __restrict__ out)
{
    extern __shared__ __align__(16) float sm[];
    float2* s_img  = reinterpret_cast<float2*>(sm);
    float2* s_pool = reinterpret_cast<float2*>(sm) + OFF_POOL_F2;
    float*  s_w    = sm + OFF_W;
    float*  s_cb   = sm + OFF_CB;
    float*  s_t    = sm + OFF_T;

    const int tid  = threadIdx.x;
    const int lane = tid & 31;
    const int wid  = tid >> 5;
    const int b0   = blockIdx.x * 2;

    // ---- stage conv weights + bias ----
    for (int idx = tid; idx < 1125; idx += THREADS) s_w[idx] = conv_w[idx];
    if (tid < 45) s_cb[tid] = conv_b[tid];

    // ---- stage the image pair, interleaved (float4 in/out) ----
    for (int idx = tid; idx < 3 * 32 * 8; idx += THREADS) {
        int grp = idx & 7;
        int row = (idx >> 3) & 31;
        int gch = idx >> 8;
        const float* pA = x + (size_t)b0 * 3072 + gch * 1024 + row * 32 + grp * 4;
        float4 a = *(const float4*)pA;
        float4 b = *(const float4*)(pA + 3072);
        float4* dst = (float4*)(s_img + gch * IMG_PLANE_F2
                                      + row * IMG_ROW_F2 + grp * 4);
        dst[0] = make_float4(a.x, b.x, a.y, b.y);
        dst[1] = make_float4(a.z, b.z, a.w, b.w);
    }
    __syncthreads();

    // ---- phase 1: packed conv + sigmoid(max-pool) ----
    for (int task = tid; task < 45 * 28; task += THREADS) {
        int c    = task % 45;
        int rest = task / 45;
        int half = rest & 1;
        int pi   = rest >> 1;

        int g  = c / 15;
        const float*  wb = s_w + c * 25;
        const float2* ib = s_img + g * IMG_PLANE_F2
                                 + (pi * 2) * IMG_ROW_F2 + half * 14;

        float2 pmax[7];
        conv_subpass<8>(ib,     wb, pmax);
        conv_subpass<6>(ib + 8, wb, pmax + 4);

        float bias = s_cb[c];
        float2* pb = s_pool + c * POOL_CH_F2 + pi * POOL_ROW_F2 + half * 7;
        #pragma unroll
        for (int pj = 0; pj < 7; pj++)
            pb[pj] = make_float2(sigmoidf_fast(pmax[pj].x + bias),
                                 sigmoidf_fast(pmax[pj].y + bias));
    }
    __syncthreads();

    // ---- phase 2: tree einsum, one warp per gi, lanes = (j,ki,kj) ----
    {
        const bool act = lane < 28;
        const int j  = lane >> 2;
        const int ki = (lane >> 1) & 1;
        const int kj = lane & 1;

        for (int gi = wid; gi < 21; gi += THREADS / 32) {
            int g = gi / 7;
            int i = gi % 7;

            // loop-invariant bases (decode hoisted out of the m loop)
            const float* wl = tree_w + g * 196 + i * 28 + j * 4 + ki * 2 + kj;
            int pbase = (g * 15) * POOL_CH_F2
                      + (2 * i + ki) * POOL_ROW_F2 + 2 * j + kj;

            float2 acc[16];
            #pragma unroll
            for (int f = 0; f < 16; f++) acc[f] = make_float2(0.f, 0.f);

            #pragma unroll 5
            for (int m = 0; m < 15; m++) {
                float2 pv = make_float2(0.f, 0.f);
                if (act) pv = s_pool[pbase + m * POOL_CH_F2];
                const float* wm = wl + m * 588;
                #pragma unroll
                for (int f = 0; f < 16; f++) {
                    float w = act ? __ldg(wm + f * 8820) : 0.f;
                    acc[f] = ffma2(pv, make_float2(w, w), acc[f]);
                }
            }

            // select-butterfly: 16 sums over 32 lanes in 4 halving steps + 1
            {
                bool b = (lane & 16) != 0;
                #pragma unroll
                for (int f = 0; f < 8; f++) {
                    float2 snd = b ? acc[f] : acc[f + 8];
                    float rx = __shfl_xor_sync(0xffffffffu, snd.x, 16);
                    float ry = __shfl_xor_sync(0xffffffffu, snd.y, 16);
                    float2 kp = b ? acc[f + 8] : acc[f];
                    acc[f] = make_float2(kp.x + rx, kp.y + ry);
                }
            }
            {
                bool b = (lane & 8) != 0;
                #pragma unroll
                for (int f = 0; f < 4; f++) {
                    float2 snd = b ? acc[f] : acc[f + 4];
                    float rx = __shfl_xor_sync(0xffffffffu, snd.x, 8);
                    float ry = __shfl_xor_sync(0xffffffffu, snd.y, 8);
                    float2 kp = b ? acc[f + 4] : acc[f];
                    acc[f] = make_float2(kp.x + rx, kp.y + ry);
                }
            }
            {
                bool b = (lane & 4) != 0;
                #pragma unroll
                for (int f = 0; f < 2; f++) {
                    float2 snd = b ? acc[f] : acc[f + 2];
                    float rx = __shfl_xor_sync(0xffffffffu, snd.x, 4);
                    float ry = __shfl_xor_sync(0xffffffffu, snd.y, 4);
                    float2 kp = b ? acc[f + 2] : acc[f];
                    acc[f] = make_float2(kp.x + rx, kp.y + ry);
                }
            }
            {
                bool b = (lane & 2) != 0;
                float2 snd = b ? acc[0] : acc[1];
                float rx = __shfl_xor_sync(0xffffffffu, snd.x, 2);
                float ry = __shfl_xor_sync(0xffffffffu, snd.y, 2);
                float2 kp = b ? acc[1] : acc[0];
                acc[0] = make_float2(kp.x + rx, kp.y + ry);
            }
            acc[0].x += __shfl_xor_sync(0xffffffffu, acc[0].x, 1);
            acc[0].y += __shfl_xor_sync(0xffffffffu, acc[0].y, 1);

            // lane (f<<1) has f = bits(4..1); even lane stores img0, odd img1
            int f   = (lane >> 1) & 15;
            int idx = f * 21 + gi;
            float tb = tree_b[idx];
            if ((lane & 1) == 0)
                s_t[      idx] = sigmoidf_fast(acc[0].x + tb);
            else
                s_t[336 + idx] = sigmoidf_fast(acc[0].y + tb);
        }
    }
    __syncthreads();

    // ---- phase 3: FC 336 -> 10 ----
    if (tid < 160) {
        int part  = tid & 7;
        int combo = tid >> 3;
        int img   = combo / 10;
        int o     = combo % 10;
        const float* tv = s_t + img * 336;
        const float* wv = fc_w + o * 336;
        float s = 0.f;
        for (int k = part; k < 336; k += 8)
            s = fmaf(tv[k], wv[k], s);
        s += __shfl_xor_sync(0xffffffffu, s, 1);
        s += __shfl_xor_sync(0xffffffffu, s, 2);
        s += __shfl_xor_sync(0xffffffffu, s, 4);
        if (part == 0)
            out[(b0 + img) * 10 + o] = s + fc_b[o];
    }
}

extern "C" void kernel_launch(void* const* d_in, const int* in_sizes, int n_in,
                              void* d_out, int out_size)
{
    const float* x      = (const float*)d_in[0];
    const float* conv_w = (const float*)d_in[1];
    const float* conv_b = (const float*)d_in[2];
    const float* tree_w = (const float*)d_in[3];
    const float* tree_b = (const float*)d_in[4];
    const float* fc_w   = (const float*)d_in[5];
    const float* fc_b   = (const float*)d_in[6];
    float* out = (float*)d_out;

    const int smem_bytes = SMEM_FLOATS * (int)sizeof(float);
    cudaFuncSetAttribute(tree3_fused,
                         cudaFuncAttributeMaxDynamicSharedMemorySize, smem_bytes);

    tree3_fused<<<BTOT / 2, THREADS, smem_bytes>>>(
        x, conv_w, conv_b, tree_w, tree_b, fc_w, fc_b, out);
}